// round 6
// baseline (speedup 1.0000x reference)
#include <cuda_runtime.h>
#include <math.h>
#include <stdint.h>

#define Bsz 8192
#define Dd  1024
#define KTOT 1024
#define CAP 10
#define NTOT 5120            // 3*D (Ux) + D (Sr) + D (Sg)

// ---- device-global scratch (allocation-free rule) ----
__device__ float g_C[(size_t)Bsz * NTOT];    // [B, 5120]: Ucx|Urx|Ugx|Sr|Sg
__device__ float g_WT[(size_t)NTOT * KTOT];  // transposed weights, tf32-rounded
__device__ float g_Ax[(size_t)Bsz * KTOT];   // x, tf32-rounded
__device__ float g_As[(size_t)Bsz * KTOT];   // state, tf32-rounded
__device__ float g_v1[CAP * Dd];
__device__ float g_v2[CAP * Dd];

__device__ __forceinline__ float tf32r(float x) {
    asm("cvt.rna.tf32.f32 %0, %0;" : "+f"(x));
    return x;
}
__device__ __forceinline__ uint32_t smem_u32(const void* p) {
    uint32_t a;
    asm("{ .reg .u64 t; cvta.to.shared.u64 t, %1; cvt.u32.u64 %0, t; }" : "=r"(a) : "l"(p));
    return a;
}
__device__ __forceinline__ void cp16(uint32_t dst, const void* src) {
    asm volatile("cp.async.cg.shared.global [%0], [%1], 16;" :: "r"(dst), "l"(src));
}
#define LDSM_X4(r0, r1, r2, r3, addr) \
    asm volatile("ldmatrix.sync.aligned.m8n8.x4.shared.b16 {%0,%1,%2,%3}, [%4];" \
                 : "=r"(r0), "=r"(r1), "=r"(r2), "=r"(r3) : "r"(addr))

// ---------------------------------------------------------------------------
// Pre-round activations to tf32 (rna, unbiased)
// ---------------------------------------------------------------------------
__global__ void __launch_bounds__(256) round_acts(const float* __restrict__ x,
                                                  const float* __restrict__ state) {
    size_t i = (size_t)blockIdx.x * 1024 + threadIdx.x * 4;
    float4 a = *(const float4*)(x + i);
    a.x = tf32r(a.x); a.y = tf32r(a.y); a.z = tf32r(a.z); a.w = tf32r(a.w);
    *(float4*)(g_Ax + i) = a;
    float4 s = *(const float4*)(state + i);
    s.x = tf32r(s.x); s.y = tf32r(s.y); s.z = tf32r(s.z); s.w = tf32r(s.w);
    *(float4*)(g_As + i) = s;
}

// ---------------------------------------------------------------------------
// Weight transpose + tf32 rounding: g_WT[n][k] = src[k][n]
// ---------------------------------------------------------------------------
__global__ void __launch_bounds__(256) transpose_weights(const float* __restrict__ U,
                                                         const float* __restrict__ Wr,
                                                         const float* __restrict__ Wg) {
    __shared__ float tile[32][33];
    const int kt = blockIdx.x * 32;
    const int nt = blockIdx.y * 32;
    const int tx = threadIdx.x & 31;
    const int ty = threadIdx.x >> 5;   // 0..7
#pragma unroll
    for (int i = 0; i < 4; i++) {
        int k = kt + ty + i * 8;
        int n = nt + tx;
        float v = (n < 3072) ? U[(size_t)k * 3072 + n]
                : (n < 4096) ? Wr[(size_t)k * 1024 + (n - 3072)]
                             : Wg[(size_t)k * 1024 + (n - 4096)];
        tile[ty + i * 8][tx] = tf32r(v);
    }
    __syncthreads();
#pragma unroll
    for (int i = 0; i < 4; i++)
        g_WT[(size_t)(nt + ty + i * 8) * KTOT + kt + tx] = tile[tx][ty + i * 8];
}

// ---------------------------------------------------------------------------
// tf32 mma.sync GEMM:  g_C[m, n] = sum_k A[m,k] * g_WT[n,k]
// CTA 128x256, BK=32, 3-stage cp.async pipeline, 8 warps (2x4), warp 64x64.
// Fragments via ldmatrix.x4. 255-reg budget (launch_bounds 256,1) so ptxas
// can pipeline LDSM across ks iterations.
// Padded smem rows (stride 36 floats = 144B): conflict-free ldmatrix.
// ---------------------------------------------------------------------------
#define BK 32
#define NCH (KTOT / BK)        // 32
#define LDSS 36                // floats per smem row
#define ROWB (LDSS * 4)        // 144 bytes per row
#define A_FLTS (128 * LDSS)    // 4608 floats
#define B_FLTS (256 * LDSS)    // 9216 floats
#define STG_FLTS (A_FLTS + B_FLTS)            // 13824 floats = 55296 B
#define GEMM_SMEM (3 * STG_FLTS * 4)          // 165888 bytes

__global__ void __launch_bounds__(256, 1) gemm_tf32(void) {
    extern __shared__ float sm[];
    const uint32_t sbase = smem_u32(sm);

    const int tid = threadIdx.x;
    const int wid = tid >> 5;
    const int lane = tid & 31;
    const int gid = lane >> 2;     // 0..7
    const int tig = lane & 3;      // 0..3
    const int wm = (wid & 1) * 64; // warp M offset
    const int wn = (wid >> 1) * 64;// warp N offset (0..192)

    const int colB = blockIdx.x * 256;
    const int rowA = blockIdx.y * 128;
    const float* Ag = ((colB < 3072) ? g_Ax : g_As) + (size_t)rowA * KTOT;
    const float* Bg = g_WT + (size_t)colB * KTOT;

    // ldmatrix lane offsets (bytes within stage):
    const uint32_t aOff = (uint32_t)(wm + (lane & 15)) * ROWB + ((lane >> 4) << 4);
    const uint32_t bOff = (uint32_t)(wn + (((lane >> 4) & 1) << 3) + (lane & 7)) * ROWB
                        + (((lane >> 3) & 1) << 4);

    float acc[4][8][4];
#pragma unroll
    for (int i = 0; i < 4; i++)
#pragma unroll
        for (int j = 0; j < 8; j++)
#pragma unroll
            for (int q = 0; q < 4; q++) acc[i][j][q] = 0.f;

    auto load_stage = [&](int chunk, int s) {
        const size_t k0 = (size_t)chunk * BK;
        const uint32_t base = sbase + (uint32_t)s * (STG_FLTS * 4);
#pragma unroll
        for (int q = 0; q < 4; q++) {            // A: 1024 float4
            int idx = tid + q * 256;
            int r = idx >> 3, c = (idx & 7) * 4;
            cp16(base + (r * LDSS + c) * 4, Ag + (size_t)r * KTOT + k0 + c);
        }
#pragma unroll
        for (int q = 0; q < 8; q++) {            // B: 2048 float4
            int idx = tid + q * 256;
            int r = idx >> 3, c = (idx & 7) * 4;
            cp16(base + A_FLTS * 4 + (r * LDSS + c) * 4, Bg + (size_t)r * KTOT + k0 + c);
        }
        asm volatile("cp.async.commit_group;");
    };

    load_stage(0, 0);
    load_stage(1, 1);
    asm volatile("cp.async.wait_group 1;");   // stage 0 ready
    __syncthreads();

    for (int ch = 0; ch < NCH; ch++) {
        const int s = ch % 3;
        if (ch + 2 < NCH) load_stage(ch + 2, (ch + 2) % 3);

        const uint32_t cA_u = sbase + (uint32_t)s * (STG_FLTS * 4);
        const uint32_t cB_u = cA_u + A_FLTS * 4;
#pragma unroll
        for (int ks = 0; ks < 4; ks++) {
            uint32_t a[4][4], b[8][2];
            const uint32_t kb = (uint32_t)ks * 32;
#pragma unroll
            for (int mt = 0; mt < 4; mt++)
                LDSM_X4(a[mt][0], a[mt][1], a[mt][2], a[mt][3],
                        cA_u + aOff + (uint32_t)mt * (16 * ROWB) + kb);
#pragma unroll
            for (int np = 0; np < 4; np++)
                LDSM_X4(b[np * 2][0], b[np * 2][1], b[np * 2 + 1][0], b[np * 2 + 1][1],
                        cB_u + bOff + (uint32_t)np * (16 * ROWB) + kb);
#pragma unroll
            for (int mt = 0; mt < 4; mt++)
#pragma unroll
                for (int nt = 0; nt < 8; nt++) {
                    float* c = acc[mt][nt];
                    asm volatile(
                        "mma.sync.aligned.m16n8k8.row.col.f32.tf32.tf32.f32 "
                        "{%0,%1,%2,%3}, {%4,%5,%6,%7}, {%8,%9}, {%0,%1,%2,%3};"
                        : "+f"(c[0]), "+f"(c[1]), "+f"(c[2]), "+f"(c[3])
                        : "r"(a[mt][0]), "r"(a[mt][1]), "r"(a[mt][2]), "r"(a[mt][3]),
                          "r"(b[nt][0]), "r"(b[nt][1]));
                }
        }
        if (ch + 1 < NCH) {
            if (ch + 2 < NCH) asm volatile("cp.async.wait_group 1;");
            else              asm volatile("cp.async.wait_group 0;");
            __syncthreads();
        }
    }

    // epilogue
#pragma unroll
    for (int mt = 0; mt < 4; mt++) {
        const int m = rowA + wm + mt * 16 + gid;
        float* crow0 = g_C + (size_t)m * NTOT + colB + wn;
        float* crow1 = crow0 + 8 * NTOT;
#pragma unroll
        for (int nt = 0; nt < 8; nt++) {
            const int n = nt * 8 + tig * 2;
            float2 lo = {acc[mt][nt][0], acc[mt][nt][1]};
            float2 hi = {acc[mt][nt][2], acc[mt][nt][3]};
            *(float2*)(crow0 + n) = lo;
            *(float2*)(crow1 + n) = hi;
        }
    }
}

// ---------------------------------------------------------------------------
// Butterfly coefficient precompute
// ---------------------------------------------------------------------------
__global__ void precompute_v(const float* __restrict__ theta) {
    int i = blockIdx.x;
    int m = threadIdx.x;
    int bl = 10 - i;
    int j = m >> bl;
    int q = m & ((1 << bl) - 1);
    int src = (q << i) + j;
    float th = theta[i * 512 + (src & 511)];
    float c = cosf(th), s = sinf(th);
    if (src >= 512) s = -s;
    g_v1[i * Dd + m] = c;
    g_v2[i * Dd + m] = s;
}

// ---------------------------------------------------------------------------
// Fused gates + butterfly + modReLU + blend.
// Thread t owns j = 4t..4t+3: smem for masks 512/256/128, shfl for 64..4,
// in-register for 2/1.
// ---------------------------------------------------------------------------
__global__ void __launch_bounds__(256) fuse_kernel(const float* __restrict__ state,
                                                   const float* __restrict__ bias_r,
                                                   const float* __restrict__ bias_g,
                                                   const float* __restrict__ bias_c,
                                                   float* __restrict__ out) {
    __shared__ float buf[2][Dd];
    const int b = blockIdx.x;
    const int t = threadIdx.x;
    const int j0 = t * 4;
    const float* crow = g_C + (size_t)b * NTOT;

    float4 s4  = *(const float4*)(state + (size_t)b * Dd + j0);
    float4 ucx = *(const float4*)(crow + j0);
    float4 urx = *(const float4*)(crow + 1024 + j0);
    float4 ugx = *(const float4*)(crow + 2048 + j0);
    float4 sr4 = *(const float4*)(crow + 3072 + j0);
    float4 sg4 = *(const float4*)(crow + 4096 + j0);
    float4 br4 = *(const float4*)(bias_r + j0);
    float4 bg4 = *(const float4*)(bias_g + j0);
    float4 bc4 = *(const float4*)(bias_c + j0);

    float st[4] = {s4.x, s4.y, s4.z, s4.w};
    float h[4]  = {s4.x, s4.y, s4.z, s4.w};
    float rr[4], gg[4];
    {
        float pr[4] = {urx.x + sr4.x + br4.x, urx.y + sr4.y + br4.y,
                       urx.z + sr4.z + br4.z, urx.w + sr4.w + br4.w};
        float pg[4] = {ugx.x + sg4.x + bg4.x, ugx.y + sg4.y + bg4.y,
                       ugx.z + sg4.z + bg4.z, ugx.w + sg4.w + bg4.w};
#pragma unroll
        for (int i = 0; i < 4; i++) {
            rr[i] = 1.f / (1.f + expf(-pr[i]));
            gg[i] = 1.f / (1.f + expf(-pg[i]));
        }
    }

#pragma unroll
    for (int sidx = 0; sidx < 3; sidx++) {
        const int mask = 512 >> sidx;
        const int tx = t ^ (mask >> 2);
        float4 v1 = *(const float4*)(g_v1 + sidx * Dd + j0);
        float4 v2 = *(const float4*)(g_v2 + sidx * Dd + j0);
        float4 p = {h[0] * v2.x, h[1] * v2.y, h[2] * v2.z, h[3] * v2.w};
        *(float4*)&buf[sidx & 1][j0] = p;
        __syncthreads();
        float4 q = *(const float4*)&buf[sidx & 1][tx * 4];
        h[0] = fmaf(h[0], v1.x, q.x);
        h[1] = fmaf(h[1], v1.y, q.y);
        h[2] = fmaf(h[2], v1.z, q.z);
        h[3] = fmaf(h[3], v1.w, q.w);
    }

#pragma unroll
    for (int sidx = 3; sidx < 8; sidx++) {
        const int mask = 512 >> sidx;
        const int lx = mask >> 2;   // 16,8,4,2,1
        float4 v1 = *(const float4*)(g_v1 + sidx * Dd + j0);
        float4 v2 = *(const float4*)(g_v2 + sidx * Dd + j0);
        float p[4] = {h[0] * v2.x, h[1] * v2.y, h[2] * v2.z, h[3] * v2.w};
        float q[4];
#pragma unroll
        for (int i = 0; i < 4; i++) q[i] = __shfl_xor_sync(0xffffffffu, p[i], lx);
        h[0] = fmaf(h[0], v1.x, q[0]);
        h[1] = fmaf(h[1], v1.y, q[1]);
        h[2] = fmaf(h[2], v1.z, q[2]);
        h[3] = fmaf(h[3], v1.w, q[3]);
    }

    {
        float4 v1 = *(const float4*)(g_v1 + 8 * Dd + j0);
        float4 v2 = *(const float4*)(g_v2 + 8 * Dd + j0);
        float v1a[4] = {v1.x, v1.y, v1.z, v1.w};
        float v2a[4] = {v2.x, v2.y, v2.z, v2.w};
        float hn[4];
#pragma unroll
        for (int i = 0; i < 4; i++) hn[i] = fmaf(h[i], v1a[i], h[i ^ 2] * v2a[i ^ 2]);
#pragma unroll
        for (int i = 0; i < 4; i++) h[i] = hn[i];
    }
    {
        float4 v1 = *(const float4*)(g_v1 + 9 * Dd + j0);
        float4 v2 = *(const float4*)(g_v2 + 9 * Dd + j0);
        float v1a[4] = {v1.x, v1.y, v1.z, v1.w};
        float v2a[4] = {v2.x, v2.y, v2.z, v2.w};
        float hn[4];
#pragma unroll
        for (int i = 0; i < 4; i++) hn[i] = fmaf(h[i], v1a[i], h[i ^ 1] * v2a[i ^ 1]);
#pragma unroll
        for (int i = 0; i < 4; i++) h[i] = hn[i];
    }

    float ux[4] = {ucx.x, ucx.y, ucx.z, ucx.w};
    float bc[4] = {bc4.x, bc4.y, bc4.z, bc4.w};
    float4 o;
    float* op = &o.x;
#pragma unroll
    for (int i = 0; i < 4; i++) {
        float pre = fmaf(rr[i], h[i], ux[i]);
        float ac = fabsf(pre) + 0.001f + bc[i];
        ac = fmaxf(ac, 0.f);
        float c = (pre > 0.f) ? ac : ((pre < 0.f) ? -ac : 0.f);
        op[i] = fmaf(gg[i], st[i] - c, c);
    }
    *(float4*)(out + (size_t)b * Dd + j0) = o;
}

// ---------------------------------------------------------------------------
extern "C" void kernel_launch(void* const* d_in, const int* in_sizes, int n_in,
                              void* d_out, int out_size) {
    const float* x      = (const float*)d_in[0];
    const float* state  = (const float*)d_in[1];
    const float* theta  = (const float*)d_in[2];
    const float* U      = (const float*)d_in[3];
    const float* W_r    = (const float*)d_in[4];
    const float* W_g    = (const float*)d_in[5];
    const float* bias_r = (const float*)d_in[6];
    const float* bias_g = (const float*)d_in[7];
    const float* bias_c = (const float*)d_in[8];
    float* out = (float*)d_out;

    cudaFuncSetAttribute(gemm_tf32, cudaFuncAttributeMaxDynamicSharedMemorySize, GEMM_SMEM);

    precompute_v<<<CAP, Dd>>>(theta);
    round_acts<<<(Bsz * KTOT) / 1024, 256>>>(x, state);

    dim3 gT(KTOT / 32, NTOT / 32);
    transpose_weights<<<gT, 256>>>(U, W_r, W_g);

    dim3 gG(NTOT / 256, Bsz / 128);   // (20, 64)
    gemm_tf32<<<gG, 256, GEMM_SMEM>>>();

    fuse_kernel<<<Bsz, 256>>>(state, bias_r, bias_g, bias_c, out);
}

// round 8
// speedup vs baseline: 1.0681x; 1.0681x over previous
#include <cuda_runtime.h>
#include <math.h>
#include <stdint.h>

#define Bsz 8192
#define Dd  1024
#define KTOT 1024
#define CAP 10
#define NTOT 5120            // 3*D (Ux) + D (Sr) + D (Sg)

// ---- device-global scratch (allocation-free rule) ----
__device__ float g_C[(size_t)Bsz * NTOT];    // [B, 5120]: Ucx|Urx|Ugx|Sr|Sg
__device__ float g_WT[(size_t)NTOT * KTOT];  // transposed weights, tf32-rounded
__device__ float g_Ax[(size_t)Bsz * KTOT];   // x, tf32-rounded
__device__ float g_As[(size_t)Bsz * KTOT];   // state, tf32-rounded
__device__ float g_v1[CAP * Dd];
__device__ float g_v2[CAP * Dd];

__device__ __forceinline__ float tf32r(float x) {
    asm("cvt.rna.tf32.f32 %0, %0;" : "+f"(x));
    return x;
}
__device__ __forceinline__ uint32_t smem_u32(const void* p) {
    uint32_t a;
    asm("{ .reg .u64 t; cvta.to.shared.u64 t, %1; cvt.u32.u64 %0, t; }" : "=r"(a) : "l"(p));
    return a;
}
__device__ __forceinline__ void cp16(uint32_t dst, const void* src) {
    asm volatile("cp.async.cg.shared.global [%0], [%1], 16;" :: "r"(dst), "l"(src));
}
#define LDSM_X4(r0, r1, r2, r3, addr) \
    asm volatile("ldmatrix.sync.aligned.m8n8.x4.shared.b16 {%0,%1,%2,%3}, [%4];" \
                 : "=r"(r0), "=r"(r1), "=r"(r2), "=r"(r3) : "r"(addr))

// ---------------------------------------------------------------------------
// Pre-round activations to tf32 (rna, unbiased)
// ---------------------------------------------------------------------------
__global__ void __launch_bounds__(256) round_acts(const float* __restrict__ x,
                                                  const float* __restrict__ state) {
    size_t i = (size_t)blockIdx.x * 1024 + threadIdx.x * 4;
    float4 a = *(const float4*)(x + i);
    a.x = tf32r(a.x); a.y = tf32r(a.y); a.z = tf32r(a.z); a.w = tf32r(a.w);
    *(float4*)(g_Ax + i) = a;
    float4 s = *(const float4*)(state + i);
    s.x = tf32r(s.x); s.y = tf32r(s.y); s.z = tf32r(s.z); s.w = tf32r(s.w);
    *(float4*)(g_As + i) = s;
}

// ---------------------------------------------------------------------------
// Weight transpose + tf32 rounding: g_WT[n][k] = src[k][n]
// ---------------------------------------------------------------------------
__global__ void __launch_bounds__(256) transpose_weights(const float* __restrict__ U,
                                                         const float* __restrict__ Wr,
                                                         const float* __restrict__ Wg) {
    __shared__ float tile[32][33];
    const int kt = blockIdx.x * 32;
    const int nt = blockIdx.y * 32;
    const int tx = threadIdx.x & 31;
    const int ty = threadIdx.x >> 5;   // 0..7
#pragma unroll
    for (int i = 0; i < 4; i++) {
        int k = kt + ty + i * 8;
        int n = nt + tx;
        float v = (n < 3072) ? U[(size_t)k * 3072 + n]
                : (n < 4096) ? Wr[(size_t)k * 1024 + (n - 3072)]
                             : Wg[(size_t)k * 1024 + (n - 4096)];
        tile[ty + i * 8][tx] = tf32r(v);
    }
    __syncthreads();
#pragma unroll
    for (int i = 0; i < 4; i++)
        g_WT[(size_t)(nt + ty + i * 8) * KTOT + kt + tx] = tile[tx][ty + i * 8];
}

// ---------------------------------------------------------------------------
// tf32 mma.sync GEMM:  g_C[m, n] = sum_k A[m,k] * g_WT[n,k]
// CTA 128x128, 128 threads (4 warps, 2x2), warp tile 64x64, BK=32,
// 3-stage cp.async pipeline. 2 CTAs/SM co-resident (regs 55.8K, smem 221KB).
// Fragments via ldmatrix.x4; padded rows (36 floats) conflict-free.
// ---------------------------------------------------------------------------
#define BK 32
#define NCH (KTOT / BK)        // 32
#define LDSS 36                // floats per smem row
#define ROWB (LDSS * 4)        // 144 bytes per row
#define OP_FLTS (128 * LDSS)   // 4608 floats per operand
#define STG_FLTS (2 * OP_FLTS) // 9216 floats per stage (36864 B)
#define GEMM_SMEM (3 * STG_FLTS * 4)   // 110592 bytes

__global__ void __launch_bounds__(128, 2) gemm_tf32(void) {
    extern __shared__ float sm[];
    const uint32_t sbase = smem_u32(sm);

    const int tid = threadIdx.x;
    const int wid = tid >> 5;
    const int lane = tid & 31;
    const int gid = lane >> 2;     // 0..7
    const int tig = lane & 3;      // 0..3
    const int wm = (wid & 1) * 64; // warp M offset (0/64)
    const int wn = (wid >> 1) * 64;// warp N offset (0/64)

    const int colB = blockIdx.x * 128;
    const int rowA = blockIdx.y * 128;
    const float* Ag = ((colB < 3072) ? g_Ax : g_As) + (size_t)rowA * KTOT;
    const float* Bg = g_WT + (size_t)colB * KTOT;

    // ldmatrix lane offsets (bytes within stage):
    const uint32_t aOff = (uint32_t)(wm + (lane & 15)) * ROWB + ((lane >> 4) << 4);
    const uint32_t bOff = (uint32_t)(wn + (((lane >> 4) & 1) << 3) + (lane & 7)) * ROWB
                        + (((lane >> 3) & 1) << 4);

    float acc[4][8][4];
#pragma unroll
    for (int i = 0; i < 4; i++)
#pragma unroll
        for (int j = 0; j < 8; j++)
#pragma unroll
            for (int q = 0; q < 4; q++) acc[i][j][q] = 0.f;

    auto load_stage = [&](int chunk, int s) {
        const size_t k0 = (size_t)chunk * BK;
        const uint32_t base = sbase + (uint32_t)s * (STG_FLTS * 4);
#pragma unroll
        for (int q = 0; q < 8; q++) {            // A: 1024 float4 / 128 thr
            int idx = tid + q * 128;
            int r = idx >> 3, c = (idx & 7) * 4;
            cp16(base + (r * LDSS + c) * 4, Ag + (size_t)r * KTOT + k0 + c);
        }
#pragma unroll
        for (int q = 0; q < 8; q++) {            // B: 1024 float4 / 128 thr
            int idx = tid + q * 128;
            int r = idx >> 3, c = (idx & 7) * 4;
            cp16(base + OP_FLTS * 4 + (r * LDSS + c) * 4, Bg + (size_t)r * KTOT + k0 + c);
        }
        asm volatile("cp.async.commit_group;");
    };

    load_stage(0, 0);
    load_stage(1, 1);
    asm volatile("cp.async.wait_group 1;");   // stage 0 ready
    __syncthreads();

    for (int ch = 0; ch < NCH; ch++) {
        const int s = ch % 3;
        if (ch + 2 < NCH) load_stage(ch + 2, (ch + 2) % 3);

        const uint32_t cA_u = sbase + (uint32_t)s * (STG_FLTS * 4);
        const uint32_t cB_u = cA_u + OP_FLTS * 4;
#pragma unroll
        for (int ks = 0; ks < 4; ks++) {
            uint32_t a[4][4], b[8][2];
            const uint32_t kb = (uint32_t)ks * 32;
#pragma unroll
            for (int mt = 0; mt < 4; mt++)
                LDSM_X4(a[mt][0], a[mt][1], a[mt][2], a[mt][3],
                        cA_u + aOff + (uint32_t)mt * (16 * ROWB) + kb);
#pragma unroll
            for (int np = 0; np < 4; np++)
                LDSM_X4(b[np * 2][0], b[np * 2][1], b[np * 2 + 1][0], b[np * 2 + 1][1],
                        cB_u + bOff + (uint32_t)np * (16 * ROWB) + kb);
#pragma unroll
            for (int mt = 0; mt < 4; mt++)
#pragma unroll
                for (int nt = 0; nt < 8; nt++) {
                    float* c = acc[mt][nt];
                    asm volatile(
                        "mma.sync.aligned.m16n8k8.row.col.f32.tf32.tf32.f32 "
                        "{%0,%1,%2,%3}, {%4,%5,%6,%7}, {%8,%9}, {%0,%1,%2,%3};"
                        : "+f"(c[0]), "+f"(c[1]), "+f"(c[2]), "+f"(c[3])
                        : "r"(a[mt][0]), "r"(a[mt][1]), "r"(a[mt][2]), "r"(a[mt][3]),
                          "r"(b[nt][0]), "r"(b[nt][1]));
                }
        }
        if (ch + 1 < NCH) {
            if (ch + 2 < NCH) asm volatile("cp.async.wait_group 1;");
            else              asm volatile("cp.async.wait_group 0;");
            __syncthreads();
        }
    }

    // epilogue: each warp writes its 64x64 tile
#pragma unroll
    for (int mt = 0; mt < 4; mt++) {
        const int m = rowA + wm + mt * 16 + gid;
        float* crow0 = g_C + (size_t)m * NTOT + colB + wn;
        float* crow1 = crow0 + 8 * NTOT;
#pragma unroll
        for (int nt = 0; nt < 8; nt++) {
            const int n = nt * 8 + tig * 2;
            float2 lo = {acc[mt][nt][0], acc[mt][nt][1]};
            float2 hi = {acc[mt][nt][2], acc[mt][nt][3]};
            *(float2*)(crow0 + n) = lo;
            *(float2*)(crow1 + n) = hi;
        }
    }
}

// ---------------------------------------------------------------------------
// Butterfly coefficient precompute
// ---------------------------------------------------------------------------
__global__ void precompute_v(const float* __restrict__ theta) {
    int i = blockIdx.x;
    int m = threadIdx.x;
    int bl = 10 - i;
    int j = m >> bl;
    int q = m & ((1 << bl) - 1);
    int src = (q << i) + j;
    float th = theta[i * 512 + (src & 511)];
    float c = cosf(th), s = sinf(th);
    if (src >= 512) s = -s;
    g_v1[i * Dd + m] = c;
    g_v2[i * Dd + m] = s;
}

// ---------------------------------------------------------------------------
// Fused gates + butterfly + modReLU + blend.
// Thread t owns j = 4t..4t+3: smem for masks 512/256/128, shfl for 64..4,
// in-register for 2/1.
// ---------------------------------------------------------------------------
__global__ void __launch_bounds__(256) fuse_kernel(const float* __restrict__ state,
                                                   const float* __restrict__ bias_r,
                                                   const float* __restrict__ bias_g,
                                                   const float* __restrict__ bias_c,
                                                   float* __restrict__ out) {
    __shared__ float buf[2][Dd];
    const int b = blockIdx.x;
    const int t = threadIdx.x;
    const int j0 = t * 4;
    const float* crow = g_C + (size_t)b * NTOT;

    float4 s4  = *(const float4*)(state + (size_t)b * Dd + j0);
    float4 ucx = *(const float4*)(crow + j0);
    float4 urx = *(const float4*)(crow + 1024 + j0);
    float4 ugx = *(const float4*)(crow + 2048 + j0);
    float4 sr4 = *(const float4*)(crow + 3072 + j0);
    float4 sg4 = *(const float4*)(crow + 4096 + j0);
    float4 br4 = *(const float4*)(bias_r + j0);
    float4 bg4 = *(const float4*)(bias_g + j0);
    float4 bc4 = *(const float4*)(bias_c + j0);

    float st[4] = {s4.x, s4.y, s4.z, s4.w};
    float h[4]  = {s4.x, s4.y, s4.z, s4.w};
    float rr[4], gg[4];
    {
        float pr[4] = {urx.x + sr4.x + br4.x, urx.y + sr4.y + br4.y,
                       urx.z + sr4.z + br4.z, urx.w + sr4.w + br4.w};
        float pg[4] = {ugx.x + sg4.x + bg4.x, ugx.y + sg4.y + bg4.y,
                       ugx.z + sg4.z + bg4.z, ugx.w + sg4.w + bg4.w};
#pragma unroll
        for (int i = 0; i < 4; i++) {
            rr[i] = 1.f / (1.f + expf(-pr[i]));
            gg[i] = 1.f / (1.f + expf(-pg[i]));
        }
    }

#pragma unroll
    for (int sidx = 0; sidx < 3; sidx++) {
        const int mask = 512 >> sidx;
        const int tx = t ^ (mask >> 2);
        float4 v1 = *(const float4*)(g_v1 + sidx * Dd + j0);
        float4 v2 = *(const float4*)(g_v2 + sidx * Dd + j0);
        float4 p = {h[0] * v2.x, h[1] * v2.y, h[2] * v2.z, h[3] * v2.w};
        *(float4*)&buf[sidx & 1][j0] = p;
        __syncthreads();
        float4 q = *(const float4*)&buf[sidx & 1][tx * 4];
        h[0] = fmaf(h[0], v1.x, q.x);
        h[1] = fmaf(h[1], v1.y, q.y);
        h[2] = fmaf(h[2], v1.z, q.z);
        h[3] = fmaf(h[3], v1.w, q.w);
    }

#pragma unroll
    for (int sidx = 3; sidx < 8; sidx++) {
        const int mask = 512 >> sidx;
        const int lx = mask >> 2;   // 16,8,4,2,1
        float4 v1 = *(const float4*)(g_v1 + sidx * Dd + j0);
        float4 v2 = *(const float4*)(g_v2 + sidx * Dd + j0);
        float p[4] = {h[0] * v2.x, h[1] * v2.y, h[2] * v2.z, h[3] * v2.w};
        float q[4];
#pragma unroll
        for (int i = 0; i < 4; i++) q[i] = __shfl_xor_sync(0xffffffffu, p[i], lx);
        h[0] = fmaf(h[0], v1.x, q[0]);
        h[1] = fmaf(h[1], v1.y, q[1]);
        h[2] = fmaf(h[2], v1.z, q[2]);
        h[3] = fmaf(h[3], v1.w, q[3]);
    }

    {
        float4 v1 = *(const float4*)(g_v1 + 8 * Dd + j0);
        float4 v2 = *(const float4*)(g_v2 + 8 * Dd + j0);
        float v1a[4] = {v1.x, v1.y, v1.z, v1.w};
        float v2a[4] = {v2.x, v2.y, v2.z, v2.w};
        float hn[4];
#pragma unroll
        for (int i = 0; i < 4; i++) hn[i] = fmaf(h[i], v1a[i], h[i ^ 2] * v2a[i ^ 2]);
#pragma unroll
        for (int i = 0; i < 4; i++) h[i] = hn[i];
    }
    {
        float4 v1 = *(const float4*)(g_v1 + 9 * Dd + j0);
        float4 v2 = *(const float4*)(g_v2 + 9 * Dd + j0);
        float v1a[4] = {v1.x, v1.y, v1.z, v1.w};
        float v2a[4] = {v2.x, v2.y, v2.z, v2.w};
        float hn[4];
#pragma unroll
        for (int i = 0; i < 4; i++) hn[i] = fmaf(h[i], v1a[i], h[i ^ 1] * v2a[i ^ 1]);
#pragma unroll
        for (int i = 0; i < 4; i++) h[i] = hn[i];
    }

    float ux[4] = {ucx.x, ucx.y, ucx.z, ucx.w};
    float bc[4] = {bc4.x, bc4.y, bc4.z, bc4.w};
    float4 o;
    float* op = &o.x;
#pragma unroll
    for (int i = 0; i < 4; i++) {
        float pre = fmaf(rr[i], h[i], ux[i]);
        float ac = fabsf(pre) + 0.001f + bc[i];
        ac = fmaxf(ac, 0.f);
        float c = (pre > 0.f) ? ac : ((pre < 0.f) ? -ac : 0.f);
        op[i] = fmaf(gg[i], st[i] - c, c);
    }
    *(float4*)(out + (size_t)b * Dd + j0) = o;
}

// ---------------------------------------------------------------------------
extern "C" void kernel_launch(void* const* d_in, const int* in_sizes, int n_in,
                              void* d_out, int out_size) {
    const float* x      = (const float*)d_in[0];
    const float* state  = (const float*)d_in[1];
    const float* theta  = (const float*)d_in[2];
    const float* U      = (const float*)d_in[3];
    const float* W_r    = (const float*)d_in[4];
    const float* W_g    = (const float*)d_in[5];
    const float* bias_r = (const float*)d_in[6];
    const float* bias_g = (const float*)d_in[7];
    const float* bias_c = (const float*)d_in[8];
    float* out = (float*)d_out;

    cudaFuncSetAttribute(gemm_tf32, cudaFuncAttributeMaxDynamicSharedMemorySize, GEMM_SMEM);

    precompute_v<<<CAP, Dd>>>(theta);
    round_acts<<<(Bsz * KTOT) / 1024, 256>>>(x, state);

    dim3 gT(KTOT / 32, NTOT / 32);
    transpose_weights<<<gT, 256>>>(U, W_r, W_g);

    dim3 gG(NTOT / 128, Bsz / 128);   // (40, 64)
    gemm_tf32<<<gG, 128, GEMM_SMEM>>>();

    fuse_kernel<<<Bsz, 256>>>(state, bias_r, bias_g, bias_c, out);
}

// round 10
// speedup vs baseline: 1.3528x; 1.2665x over previous
#include <cuda_runtime.h>
#include <math.h>
#include <stdint.h>

#define Bsz 8192
#define Dd  1024
#define KTOT 1024
#define CAP 10
#define NTOT 5120            // 3*D (Ux) + D (Sr) + D (Sg)

// ---- device-global scratch (allocation-free rule) ----
__device__ float g_C[(size_t)Bsz * NTOT];    // [B, 5120]: Ucx|Urx|Ugx|Sr|Sg
__device__ float g_WT[(size_t)NTOT * KTOT];  // transposed weights, tf32-rounded
__device__ float g_Ax[(size_t)Bsz * KTOT];   // x, tf32-rounded
__device__ float g_As[(size_t)Bsz * KTOT];   // state, tf32-rounded
__device__ float g_v1[CAP * Dd];
__device__ float g_v2[CAP * Dd];

__device__ __forceinline__ float tf32r(float x) {
    asm("cvt.rna.tf32.f32 %0, %0;" : "+f"(x));
    return x;
}
__device__ __forceinline__ uint32_t smem_u32(const void* p) {
    uint32_t a;
    asm("{ .reg .u64 t; cvta.to.shared.u64 t, %1; cvt.u32.u64 %0, t; }" : "=r"(a) : "l"(p));
    return a;
}
__device__ __forceinline__ void cp16(uint32_t dst, const void* src) {
    asm volatile("cp.async.cg.shared.global [%0], [%1], 16;" :: "r"(dst), "l"(src));
}
__device__ __forceinline__ void mbar_init(uint32_t a, uint32_t cnt) {
    asm volatile("mbarrier.init.shared.b64 [%0], %1;" :: "r"(a), "r"(cnt) : "memory");
}
__device__ __forceinline__ void mbar_wait(uint32_t a, uint32_t parity) {
    asm volatile("{\n\t.reg .pred P;\n\tWL%=:\n\t"
                 "mbarrier.try_wait.parity.acquire.cta.shared::cta.b64 P, [%0], %1, 0x989680;\n\t"
                 "@!P bra WL%=;\n\t}" :: "r"(a), "r"(parity) : "memory");
}
__device__ __forceinline__ void mbar_arrive(uint32_t a) {
    asm volatile("mbarrier.arrive.release.cta.shared::cta.b64 _, [%0];" :: "r"(a) : "memory");
}
// .noinc: the async arrive consumes one of the barrier's initialized expected
// arrivals (default form is phase-neutral: +1 pend then -1 -> deadlock).
__device__ __forceinline__ void cpasync_mbar_arrive(uint32_t a) {
    asm volatile("cp.async.mbarrier.arrive.noinc.shared.b64 [%0];" :: "r"(a) : "memory");
}
#define LDSM_X4(r0, r1, r2, r3, addr) \
    asm volatile("ldmatrix.sync.aligned.m8n8.x4.shared.b16 {%0,%1,%2,%3}, [%4];" \
                 : "=r"(r0), "=r"(r1), "=r"(r2), "=r"(r3) : "r"(addr))

// ---------------------------------------------------------------------------
// Pre-round activations to tf32 (rna, unbiased)
// ---------------------------------------------------------------------------
__global__ void __launch_bounds__(256) round_acts(const float* __restrict__ x,
                                                  const float* __restrict__ state) {
    size_t i = (size_t)blockIdx.x * 1024 + threadIdx.x * 4;
    float4 a = *(const float4*)(x + i);
    a.x = tf32r(a.x); a.y = tf32r(a.y); a.z = tf32r(a.z); a.w = tf32r(a.w);
    *(float4*)(g_Ax + i) = a;
    float4 s = *(const float4*)(state + i);
    s.x = tf32r(s.x); s.y = tf32r(s.y); s.z = tf32r(s.z); s.w = tf32r(s.w);
    *(float4*)(g_As + i) = s;
}

// ---------------------------------------------------------------------------
// Weight transpose + tf32 rounding: g_WT[n][k] = src[k][n]
// ---------------------------------------------------------------------------
__global__ void __launch_bounds__(256) transpose_weights(const float* __restrict__ U,
                                                         const float* __restrict__ Wr,
                                                         const float* __restrict__ Wg) {
    __shared__ float tile[32][33];
    const int kt = blockIdx.x * 32;
    const int nt = blockIdx.y * 32;
    const int tx = threadIdx.x & 31;
    const int ty = threadIdx.x >> 5;   // 0..7
#pragma unroll
    for (int i = 0; i < 4; i++) {
        int k = kt + ty + i * 8;
        int n = nt + tx;
        float v = (n < 3072) ? U[(size_t)k * 3072 + n]
                : (n < 4096) ? Wr[(size_t)k * 1024 + (n - 3072)]
                             : Wg[(size_t)k * 1024 + (n - 4096)];
        tile[ty + i * 8][tx] = tf32r(v);
    }
    __syncthreads();
#pragma unroll
    for (int i = 0; i < 4; i++)
        g_WT[(size_t)(nt + ty + i * 8) * KTOT + kt + tx] = tile[tx][ty + i * 8];
}

// ---------------------------------------------------------------------------
// tf32 mma.sync GEMM:  g_C[m, n] = sum_k A[m,k] * g_WT[n,k]
// CTA 128x128, 256 thr (8 warps, 2x4), warp 64x32, BK=32, 3 smem stages.
// Producer/consumer mbarrier pipeline: per-stage full[s] (256 .noinc cp.async
// arrivals) / empty[s] (256 thread arrivals) replaces wait_group+syncthreads,
// allowing warps to drift up to one chunk past each other.
// ---------------------------------------------------------------------------
#define BK 32
#define NCH (KTOT / BK)        // 32
#define LDSS 36                // floats per smem row
#define ROWB (LDSS * 4)        // 144 bytes per row
#define STG_FLTS (2 * 128 * LDSS)             // 9216 floats per stage
#define MBAR_OFF (3 * STG_FLTS * 4)           // barriers after stage buffers
#define GEMM_SMEM (MBAR_OFF + 64)             // 110656 bytes

__global__ void __launch_bounds__(256, 2) gemm_tf32(void) {
    extern __shared__ float sm[];
    const uint32_t sbase = smem_u32(sm);

    const int tid = threadIdx.x;
    const int wid = tid >> 5;
    const int lane = tid & 31;
    const int gid = lane >> 2;     // 0..7
    const int tig = lane & 3;      // 0..3
    const int wm = (wid & 1) * 64; // warp M offset
    const int wn = (wid >> 1) * 32;// warp N offset

    const int colB = blockIdx.x * 128;
    const int rowA = blockIdx.y * 128;
    const float* Ag = ((colB < 3072) ? g_Ax : g_As) + (size_t)rowA * KTOT;
    const float* Bg = g_WT + (size_t)colB * KTOT;

    // mbarriers: full[0..2] at MBAR_OFF, empty[0..2] at MBAR_OFF+24
    if (tid == 0) {
#pragma unroll
        for (int s = 0; s < 3; s++) {
            mbar_init(sbase + MBAR_OFF + s * 8, 256);        // full
            mbar_init(sbase + MBAR_OFF + 24 + s * 8, 256);   // empty
        }
    }
    __syncthreads();

    // ldmatrix lane offsets (bytes within stage):
    const uint32_t aOff = (uint32_t)(wm + (lane & 15)) * ROWB + ((lane >> 4) << 4);
    const uint32_t bOff = (uint32_t)(wn + (((lane >> 4) & 1) << 3) + (lane & 7)) * ROWB
                        + (((lane >> 3) & 1) << 4);

    float acc[4][4][4];
#pragma unroll
    for (int i = 0; i < 4; i++)
#pragma unroll
        for (int j = 0; j < 4; j++)
#pragma unroll
            for (int q = 0; q < 4; q++) acc[i][j][q] = 0.f;

    auto load_stage = [&](int chunk, int s) {
        const size_t k0 = (size_t)chunk * BK;
        const uint32_t base = sbase + (uint32_t)s * (STG_FLTS * 4);
#pragma unroll
        for (int q = 0; q < 4; q++) {            // A: 1024 float4
            int idx = tid + q * 256;
            int r = idx >> 3, c = (idx & 7) * 4;
            cp16(base + (r * LDSS + c) * 4, Ag + (size_t)r * KTOT + k0 + c);
        }
#pragma unroll
        for (int q = 0; q < 4; q++) {            // B: 1024 float4
            int idx = tid + q * 256;
            int r = idx >> 3, c = (idx & 7) * 4;
            cp16(base + (128 * LDSS) * 4 + (r * LDSS + c) * 4,
                 Bg + (size_t)r * KTOT + k0 + c);
        }
        cpasync_mbar_arrive(sbase + MBAR_OFF + (uint32_t)s * 8);
    };

    load_stage(0, 0);
    load_stage(1, 1);

    for (int ch = 0; ch < NCH; ch++) {
        const int s = ch % 3;
        // consume: wait full[s] (load number ch/3 of this stage)
        mbar_wait(sbase + MBAR_OFF + (uint32_t)s * 8, (uint32_t)((ch / 3) & 1));

        const uint32_t cA_u = sbase + (uint32_t)s * (STG_FLTS * 4);
        const uint32_t cB_u = cA_u + (128 * LDSS) * 4;
#pragma unroll
        for (int ks = 0; ks < 4; ks++) {
            uint32_t a[4][4], b[4][2];
            const uint32_t kb = (uint32_t)ks * 32;
#pragma unroll
            for (int mt = 0; mt < 4; mt++)
                LDSM_X4(a[mt][0], a[mt][1], a[mt][2], a[mt][3],
                        cA_u + aOff + (uint32_t)mt * (16 * ROWB) + kb);
#pragma unroll
            for (int np = 0; np < 2; np++)
                LDSM_X4(b[np * 2][0], b[np * 2][1], b[np * 2 + 1][0], b[np * 2 + 1][1],
                        cB_u + bOff + (uint32_t)np * (16 * ROWB) + kb);
#pragma unroll
            for (int mt = 0; mt < 4; mt++)
#pragma unroll
                for (int nt = 0; nt < 4; nt++) {
                    float* c = acc[mt][nt];
                    asm volatile(
                        "mma.sync.aligned.m16n8k8.row.col.f32.tf32.tf32.f32 "
                        "{%0,%1,%2,%3}, {%4,%5,%6,%7}, {%8,%9}, {%0,%1,%2,%3};"
                        : "+f"(c[0]), "+f"(c[1]), "+f"(c[2]), "+f"(c[3])
                        : "r"(a[mt][0]), "r"(a[mt][1]), "r"(a[mt][2]), "r"(a[mt][3]),
                          "r"(b[nt][0]), "r"(b[nt][1]));
                }
        }
        // release stage s
        mbar_arrive(sbase + MBAR_OFF + 24 + (uint32_t)s * 8);

        // produce chunk ch+2 into stage (ch+2)%3 (stage last used by chunk ch-1)
        if (ch + 2 < NCH) {
            const int s2 = (ch + 2) % 3;
            if (ch >= 1)
                mbar_wait(sbase + MBAR_OFF + 24 + (uint32_t)s2 * 8,
                          (uint32_t)(((ch - 1) / 3) & 1));
            load_stage(ch + 2, s2);
        }
    }

    // epilogue
#pragma unroll
    for (int mt = 0; mt < 4; mt++) {
        const int m = rowA + wm + mt * 16 + gid;
        float* crow0 = g_C + (size_t)m * NTOT + colB + wn;
        float* crow1 = crow0 + 8 * NTOT;
#pragma unroll
        for (int nt = 0; nt < 4; nt++) {
            const int n = nt * 8 + tig * 2;
            float2 lo = {acc[mt][nt][0], acc[mt][nt][1]};
            float2 hi = {acc[mt][nt][2], acc[mt][nt][3]};
            *(float2*)(crow0 + n) = lo;
            *(float2*)(crow1 + n) = hi;
        }
    }
}

// ---------------------------------------------------------------------------
// Butterfly coefficient precompute
// ---------------------------------------------------------------------------
__global__ void precompute_v(const float* __restrict__ theta) {
    int i = blockIdx.x;
    int m = threadIdx.x;
    int bl = 10 - i;
    int j = m >> bl;
    int q = m & ((1 << bl) - 1);
    int src = (q << i) + j;
    float th = theta[i * 512 + (src & 511)];
    float c = cosf(th), s = sinf(th);
    if (src >= 512) s = -s;
    g_v1[i * Dd + m] = c;
    g_v2[i * Dd + m] = s;
}

// ---------------------------------------------------------------------------
// Fused gates + butterfly + modReLU + blend.
// Thread t owns j = 4t..4t+3: smem for masks 512/256/128, shfl for 64..4,
// in-register for 2/1.
// ---------------------------------------------------------------------------
__global__ void __launch_bounds__(256) fuse_kernel(const float* __restrict__ state,
                                                   const float* __restrict__ bias_r,
                                                   const float* __restrict__ bias_g,
                                                   const float* __restrict__ bias_c,
                                                   float* __restrict__ out) {
    __shared__ float buf[2][Dd];
    const int b = blockIdx.x;
    const int t = threadIdx.x;
    const int j0 = t * 4;
    const float* crow = g_C + (size_t)b * NTOT;

    float4 s4  = *(const float4*)(state + (size_t)b * Dd + j0);
    float4 ucx = *(const float4*)(crow + j0);
    float4 urx = *(const float4*)(crow + 1024 + j0);
    float4 ugx = *(const float4*)(crow + 2048 + j0);
    float4 sr4 = *(const float4*)(crow + 3072 + j0);
    float4 sg4 = *(const float4*)(crow + 4096 + j0);
    float4 br4 = *(const float4*)(bias_r + j0);
    float4 bg4 = *(const float4*)(bias_g + j0);
    float4 bc4 = *(const float4*)(bias_c + j0);

    float st[4] = {s4.x, s4.y, s4.z, s4.w};
    float h[4]  = {s4.x, s4.y, s4.z, s4.w};
    float rr[4], gg[4];
    {
        float pr[4] = {urx.x + sr4.x + br4.x, urx.y + sr4.y + br4.y,
                       urx.z + sr4.z + br4.z, urx.w + sr4.w + br4.w};
        float pg[4] = {ugx.x + sg4.x + bg4.x, ugx.y + sg4.y + bg4.y,
                       ugx.z + sg4.z + bg4.z, ugx.w + sg4.w + bg4.w};
#pragma unroll
        for (int i = 0; i < 4; i++) {
            rr[i] = 1.f / (1.f + expf(-pr[i]));
            gg[i] = 1.f / (1.f + expf(-pg[i]));
        }
    }

#pragma unroll
    for (int sidx = 0; sidx < 3; sidx++) {
        const int mask = 512 >> sidx;
        const int tx = t ^ (mask >> 2);
        float4 v1 = *(const float4*)(g_v1 + sidx * Dd + j0);
        float4 v2 = *(const float4*)(g_v2 + sidx * Dd + j0);
        float4 p = {h[0] * v2.x, h[1] * v2.y, h[2] * v2.z, h[3] * v2.w};
        *(float4*)&buf[sidx & 1][j0] = p;
        __syncthreads();
        float4 q = *(const float4*)&buf[sidx & 1][tx * 4];
        h[0] = fmaf(h[0], v1.x, q.x);
        h[1] = fmaf(h[1], v1.y, q.y);
        h[2] = fmaf(h[2], v1.z, q.z);
        h[3] = fmaf(h[3], v1.w, q.w);
    }

#pragma unroll
    for (int sidx = 3; sidx < 8; sidx++) {
        const int mask = 512 >> sidx;
        const int lx = mask >> 2;   // 16,8,4,2,1
        float4 v1 = *(const float4*)(g_v1 + sidx * Dd + j0);
        float4 v2 = *(const float4*)(g_v2 + sidx * Dd + j0);
        float p[4] = {h[0] * v2.x, h[1] * v2.y, h[2] * v2.z, h[3] * v2.w};
        float q[4];
#pragma unroll
        for (int i = 0; i < 4; i++) q[i] = __shfl_xor_sync(0xffffffffu, p[i], lx);
        h[0] = fmaf(h[0], v1.x, q[0]);
        h[1] = fmaf(h[1], v1.y, q[1]);
        h[2] = fmaf(h[2], v1.z, q[2]);
        h[3] = fmaf(h[3], v1.w, q[3]);
    }

    {
        float4 v1 = *(const float4*)(g_v1 + 8 * Dd + j0);
        float4 v2 = *(const float4*)(g_v2 + 8 * Dd + j0);
        float v1a[4] = {v1.x, v1.y, v1.z, v1.w};
        float v2a[4] = {v2.x, v2.y, v2.z, v2.w};
        float hn[4];
#pragma unroll
        for (int i = 0; i < 4; i++) hn[i] = fmaf(h[i], v1a[i], h[i ^ 2] * v2a[i ^ 2]);
#pragma unroll
        for (int i = 0; i < 4; i++) h[i] = hn[i];
    }
    {
        float4 v1 = *(const float4*)(g_v1 + 9 * Dd + j0);
        float4 v2 = *(const float4*)(g_v2 + 9 * Dd + j0);
        float v1a[4] = {v1.x, v1.y, v1.z, v1.w};
        float v2a[4] = {v2.x, v2.y, v2.z, v2.w};
        float hn[4];
#pragma unroll
        for (int i = 0; i < 4; i++) hn[i] = fmaf(h[i], v1a[i], h[i ^ 1] * v2a[i ^ 1]);
#pragma unroll
        for (int i = 0; i < 4; i++) h[i] = hn[i];
    }

    float ux[4] = {ucx.x, ucx.y, ucx.z, ucx.w};
    float bc[4] = {bc4.x, bc4.y, bc4.z, bc4.w};
    float4 o;
    float* op = &o.x;
#pragma unroll
    for (int i = 0; i < 4; i++) {
        float pre = fmaf(rr[i], h[i], ux[i]);
        float ac = fabsf(pre) + 0.001f + bc[i];
        ac = fmaxf(ac, 0.f);
        float c = (pre > 0.f) ? ac : ((pre < 0.f) ? -ac : 0.f);
        op[i] = fmaf(gg[i], st[i] - c, c);
    }
    *(float4*)(out + (size_t)b * Dd + j0) = o;
}

// ---------------------------------------------------------------------------
extern "C" void kernel_launch(void* const* d_in, const int* in_sizes, int n_in,
                              void* d_out, int out_size) {
    const float* x      = (const float*)d_in[0];
    const float* state  = (const float*)d_in[1];
    const float* theta  = (const float*)d_in[2];
    const float* U      = (const float*)d_in[3];
    const float* W_r    = (const float*)d_in[4];
    const float* W_g    = (const float*)d_in[5];
    const float* bias_r = (const float*)d_in[6];
    const float* bias_g = (const float*)d_in[7];
    const float* bias_c = (const float*)d_in[8];
    float* out = (float*)d_out;

    cudaFuncSetAttribute(gemm_tf32, cudaFuncAttributeMaxDynamicSharedMemorySize, GEMM_SMEM);

    precompute_v<<<CAP, Dd>>>(theta);
    round_acts<<<(Bsz * KTOT) / 1024, 256>>>(x, state);

    dim3 gT(KTOT / 32, NTOT / 32);
    transpose_weights<<<gT, 256>>>(U, W_r, W_g);

    dim3 gG(NTOT / 128, Bsz / 128);   // (40, 64)
    gemm_tf32<<<gG, 256, GEMM_SMEM>>>();

    fuse_kernel<<<Bsz, 256>>>(state, bias_r, bias_g, bias_c, out);
}